// round 9
// baseline (speedup 1.0000x reference)
#include <cuda_runtime.h>
#include <cuda_fp16.h>
#include <math.h>
#include <stdint.h>

#define BB 4
#define TT 2048
#define CC 1024
#define HH 16
#define DHH 64
#define MROWS (BB*TT)     // 8192
#define NQKV (3*CC)       // 3072

// ------------------------------- scratch (no allocs allowed) ----------------
__device__ __half g_xh[(size_t)MROWS*CC];
__device__ __half g_xl[(size_t)MROWS*CC];
__device__ __half g_wt[(size_t)NQKV*CC];     // QKV weights, fp16, [N][K]
__device__ __half g_wot[(size_t)CC*CC];      // Wo^T, fp16, [N][K]
__device__ float  g_bias[NQKV];
__device__ float  g_qkv[(size_t)MROWS*NQKV];
__device__ __half g_kh [(size_t)BB*HH*TT*DHH];   // K fp16 [bh][t][d]
__device__ __half g_vth[(size_t)BB*HH*DHH*TT];   // V hi fp16 [bh][d][t]
__device__ __half g_vtl[(size_t)BB*HH*DHH*TT];   // V lo fp16 [bh][d][t]
__device__ __half g_ath[(size_t)MROWS*CC];
__device__ __half g_atl[(size_t)MROWS*CC];

// ------------------------------- PTX helpers --------------------------------
__device__ __forceinline__ uint32_t smem_u32(const void* p) {
    uint32_t a;
    asm("{ .reg .u64 t; cvta.to.shared.u64 t, %1; cvt.u32.u64 %0, t; }" : "=r"(a) : "l"(p));
    return a;
}
__device__ __forceinline__ void cp16(uint32_t dst, const void* src) {
    asm volatile("cp.async.cg.shared.global [%0], [%1], 16;" :: "r"(dst), "l"(src));
}
#define CP_COMMIT() asm volatile("cp.async.commit_group;" ::: "memory")
#define CP_WAIT1()  asm volatile("cp.async.wait_group 1;" ::: "memory")
#define CP_WAIT0()  asm volatile("cp.async.wait_group 0;" ::: "memory")
__device__ __forceinline__ void ldm_x4(uint32_t* r, uint32_t addr) {
    asm volatile("ldmatrix.sync.aligned.m8n8.x4.shared.b16 {%0,%1,%2,%3}, [%4];"
                 : "=r"(r[0]), "=r"(r[1]), "=r"(r[2]), "=r"(r[3]) : "r"(addr));
}
__device__ __forceinline__ void mma16816(float* d, const uint32_t* a, const uint32_t* b) {
    asm volatile(
        "mma.sync.aligned.m16n8k16.row.col.f32.f16.f16.f32 "
        "{%0,%1,%2,%3}, {%4,%5,%6,%7}, {%8,%9}, {%0,%1,%2,%3};"
        : "+f"(d[0]), "+f"(d[1]), "+f"(d[2]), "+f"(d[3])
        : "r"(a[0]), "r"(a[1]), "r"(a[2]), "r"(a[3]), "r"(b[0]), "r"(b[1]));
}
__device__ __forceinline__ uint32_t pack_f16(float v0, float v1) {
    uint32_t r;
    asm("cvt.rn.f16x2.f32 %0, %1, %2;" : "=r"(r) : "f"(v1), "f"(v0));
    return r;
}
__device__ __forceinline__ void split2h(float v0, float v1, uint32_t& hp, uint32_t& lp) {
    hp = pack_f16(v0, v1);
    __half2 h = *reinterpret_cast<__half2*>(&hp);
    float2 f = __half22float2(h);
    lp = pack_f16(v0 - f.x, v1 - f.y);
}

// ------------------------------- conversion ---------------------------------
__global__ __launch_bounds__(256) void conv_split(
    const float4* __restrict__ src, uint32_t* __restrict__ hi,
    uint32_t* __restrict__ lo, int n4)
{
    int i = blockIdx.x * blockDim.x + threadIdx.x;
    if (i >= n4) return;
    float4 v = src[i];
    uint32_t h0, l0, h1, l1;
    split2h(v.x, v.y, h0, l0);
    split2h(v.z, v.w, h1, l1);
    hi[2*i] = h0; hi[2*i+1] = h1;
    lo[2*i] = l0; lo[2*i+1] = l1;
}

__global__ __launch_bounds__(256) void repack_qkv(
    const float* __restrict__ Wq, const float* __restrict__ Wk, const float* __restrict__ Wv,
    const float* __restrict__ bq, const float* __restrict__ bk, const float* __restrict__ bv)
{
    int n = blockIdx.x;                    // 0..3071
    int p = n >> 10, w = n & 1023;
    int h = w >> 6, d = w & 63;
    const float* W = (p == 0) ? Wq : (p == 1) ? Wk : Wv;
    const float* bsrc = (p == 0) ? bq : (p == 1) ? bk : bv;
    for (int c = threadIdx.x; c < CC; c += 256)
        g_wt[(size_t)n * CC + c] = __float2half_rn(W[((size_t)h * CC + c) * DHH + d]);
    if (threadIdx.x == 0) g_bias[n] = bsrc[w];
}

__global__ __launch_bounds__(256) void repack_wo(const float* __restrict__ Wo)
{
    int n = blockIdx.x;
    for (int c = threadIdx.x; c < CC; c += 256)
        g_wot[(size_t)n * CC + c] = __float2half_rn(Wo[(size_t)c * CC + n]);
}

// preconvert K (fp16 [bh][t][d]) and V (fp16 hi/lo transposed [bh][d][t])
__global__ __launch_bounds__(256) void conv_kv(const float* __restrict__ qkv)
{
    const int bh = blockIdx.y;
    const int b = bh >> 4, h = bh & 15;
    const int t0 = blockIdx.x * 64;
    const int tid = threadIdx.x;
    const float* kg = qkv + (size_t)(b * TT) * NQKV + CC + h * DHH;
    const float* vg = qkv + (size_t)(b * TT) * NQKV + 2 * CC + h * DHH;
    __half* kd = g_kh + (size_t)bh * TT * DHH;

    #pragma unroll
    for (int it = 0; it < 2; ++it) {
        int id = it * 256 + tid;
        int r = id >> 3, s = id & 7;
        const float* src = kg + (size_t)(t0 + r) * NQKV + s * 8;
        float4 a = *reinterpret_cast<const float4*>(src);
        float4 c = *reinterpret_cast<const float4*>(src + 4);
        uint4 o;
        o.x = pack_f16(a.x, a.y); o.y = pack_f16(a.z, a.w);
        o.z = pack_f16(c.x, c.y); o.w = pack_f16(c.z, c.w);
        *reinterpret_cast<uint4*>(kd + (size_t)(t0 + r) * DHH + s * 8) = o;
    }

    const int d  = tid & 63;
    const int tg = tid >> 6;
    #pragma unroll
    for (int it = 0; it < 2; ++it) {
        int tt = t0 + it * 32 + tg * 8;
        float v[8];
        #pragma unroll
        for (int j = 0; j < 8; ++j)
            v[j] = vg[(size_t)(tt + j) * NQKV + d];
        uint4 hi, lo;
        split2h(v[0], v[1], hi.x, lo.x);
        split2h(v[2], v[3], hi.y, lo.y);
        split2h(v[4], v[5], hi.z, lo.z);
        split2h(v[6], v[7], hi.w, lo.w);
        size_t off = ((size_t)bh * DHH + d) * TT + tt;
        *reinterpret_cast<uint4*>(g_vth + off) = hi;
        *reinterpret_cast<uint4*>(g_vtl + off) = lo;
    }
}

// ------------------------------- mma.sync GEMM (512 thr, 3-stage) -----------
// C[m0:+128, n0:+128] = (Ah [+ Al if n0>=vstart]) @ B^T + bias
// 16 warps, warp tile 32x32.
#define KCH 64
#define NCH (CC / KCH)        // 16 chunks
#define TILEB 16384           // 128 rows x 128 B
#define GST (3 * TILEB)       // 48 KB / stage
#define SMEM_GEMM (3 * GST)   // 144 KB

__global__ void __launch_bounds__(512, 1) gemm_fp16x2(
    const __half* __restrict__ Ah, const __half* __restrict__ Al,
    const __half* __restrict__ B,
    const float* __restrict__ bias, float* __restrict__ C, int ldc, int vstart)
{
    extern __shared__ char dsm[];
    const uint32_t sbase = smem_u32(dsm);
    const int tid = threadIdx.x;
    const int l   = tid & 31;
    const int wid = tid >> 5;       // 0..15
    const int wm  = wid & 3;        // 4 m-blocks of 32
    const int wn  = wid >> 2;       // 4 n-blocks of 32
    const int m0  = blockIdx.x * 128;
    const int n0  = blockIdx.y * 128;
    const bool twoPass = (n0 >= vstart);

    // cp.async: 3072 granules of 16B per chunk; 6 per thread
    const __half* gptr[6];
    uint32_t srel[6];
    bool gact[6];
    {
        const __half* bases[3] = {Ah, Al, B};
        #pragma unroll
        for (int it = 0; it < 6; ++it) {
            int g = it * 512 + tid;
            int tile = g >> 10;
            int r = (g >> 3) & 127;
            int slot = g & 7;
            int row0 = (tile < 2) ? m0 : n0;
            gptr[it] = bases[tile] + (size_t)(row0 + r) * CC + slot * 8;
            srel[it] = tile * TILEB + r * 128 + ((slot ^ (r & 7)) << 4);
            gact[it] = (tile != 1) || twoPass;
        }
    }

    const int hA = l >> 4;
    uint32_t aBase[2]; int ax[2];
    #pragma unroll
    for (int i = 0; i < 2; ++i) {
        int rr = wm * 32 + (l & 15) + i * 16;
        aBase[i] = (uint32_t)(rr * 128); ax[i] = rr & 7;
    }
    const int hB = (l >> 3) & 1;
    uint32_t bBase[2]; int bx[2];
    #pragma unroll
    for (int j = 0; j < 2; ++j) {
        int rr = wn * 32 + ((l & 7) | ((l >> 4) << 3)) + j * 16;
        bBase[j] = (uint32_t)(rr * 128); bx[j] = rr & 7;
    }

    float acc[2][4][4] = {};

    // prologue: stages 0,1
    #pragma unroll
    for (int pc = 0; pc < 2; ++pc) {
        const uint32_t sb2 = sbase + pc * GST;
        const int kadv = pc * KCH;
        #pragma unroll
        for (int it = 0; it < 6; ++it)
            if (gact[it]) cp16(sb2 + srel[it], gptr[it] + kadv);
        CP_COMMIT();
    }

    int stage = 0;
    for (int c = 0; c < NCH; ++c) {
        if (c + 1 < NCH) CP_WAIT1(); else CP_WAIT0();
        __syncthreads();
        if (c + 2 < NCH) {
            const int sn = (stage + 2 >= 3) ? stage - 1 : stage + 2;
            const uint32_t sb2 = sbase + sn * GST;
            const int kadv = (c + 2) * KCH;
            #pragma unroll
            for (int it = 0; it < 6; ++it)
                if (gact[it]) cp16(sb2 + srel[it], gptr[it] + kadv);
            CP_COMMIT();
        }

        const uint32_t st = sbase + stage * GST;
        const uint32_t sAh = st, sAl = st + TILEB, sB = st + 2 * TILEB;
        #pragma unroll
        for (int ks = 0; ks < 4; ++ks) {
            const int slA = ks * 2 + hA;
            const int slB = ks * 2 + hB;
            uint32_t ah[2][4], al_[2][4], bf[4][2];
            #pragma unroll
            for (int i = 0; i < 2; ++i) {
                uint32_t off = aBase[i] + (uint32_t)((slA ^ ax[i]) << 4);
                ldm_x4(ah[i], sAh + off);
                if (twoPass) ldm_x4(al_[i], sAl + off);
            }
            #pragma unroll
            for (int j = 0; j < 2; ++j) {
                uint32_t t[4];
                ldm_x4(t, sB + bBase[j] + (uint32_t)((slB ^ bx[j]) << 4));
                bf[2*j][0] = t[0]; bf[2*j][1] = t[1];
                bf[2*j+1][0] = t[2]; bf[2*j+1][1] = t[3];
            }
            #pragma unroll
            for (int i = 0; i < 2; ++i)
                #pragma unroll
                for (int j = 0; j < 4; ++j) {
                    mma16816(acc[i][j], ah[i], bf[j]);
                    if (twoPass) mma16816(acc[i][j], al_[i], bf[j]);
                }
        }
        stage = (stage + 1 == 3) ? 0 : stage + 1;
    }

    #pragma unroll
    for (int i = 0; i < 2; ++i) {
        const int m = m0 + wm * 32 + i * 16 + (l >> 2);
        #pragma unroll
        for (int j = 0; j < 4; ++j) {
            const int n = n0 + wn * 32 + j * 8 + 2 * (l & 3);
            const float b0 = bias[n], b1 = bias[n + 1];
            float2 v0 = { acc[i][j][0] + b0, acc[i][j][1] + b1 };
            float2 v1 = { acc[i][j][2] + b0, acc[i][j][3] + b1 };
            *reinterpret_cast<float2*>(&C[(size_t)m * ldc + n]) = v0;
            *reinterpret_cast<float2*>(&C[(size_t)(m + 8) * ldc + n]) = v1;
        }
    }
}

// ------------------------------- mma flash attention (512 thr, 256 q/CTA) ---
// stage (24KB): K[64 keys][128B] @0, Vth[64 dims][128B] @8192, Vtl @16384
// Q phase reuses stage memory: Qh rows 0..255 (32KB).
#define ASTG 24576
#define SMEM_ATTN (3 * ASTG)   // 72 KB
#define QPC 256                // queries per CTA

__global__ void __launch_bounds__(512, 1) attn_mma(
    const float* __restrict__ qkv,
    __half* __restrict__ ath, __half* __restrict__ atl)
{
    extern __shared__ char smem[];
    const uint32_t sb = smem_u32(smem);
    const int tid = threadIdx.x;
    const int l   = tid & 31;
    const int wq  = tid >> 5;              // 0..15, 16 queries each
    const int bh  = blockIdx.y;
    const int b   = bh >> 4, h = bh & 15;
    const int qt  = gridDim.x - 1 - blockIdx.x;
    const int q0  = qt * QPC;

    const float scale = 0.03125f;
    const float* qg = qkv + ((size_t)(b * TT + q0)) * NQKV + h * DHH;

    // ---- load Q (256 rows), scale, cast fp16, store smem ----
    #pragma unroll
    for (int it = 0; it < 4; ++it) {
        int id = it * 512 + tid;
        int row = id >> 3, sl = id & 7;
        float4 a = *reinterpret_cast<const float4*>(qg + (size_t)row * NQKV + sl * 8);
        float4 c = *reinterpret_cast<const float4*>(qg + (size_t)row * NQKV + sl * 8 + 4);
        uint4 o;
        o.x = pack_f16(a.x * scale, a.y * scale);
        o.y = pack_f16(a.z * scale, a.w * scale);
        o.z = pack_f16(c.x * scale, c.y * scale);
        o.w = pack_f16(c.z * scale, c.w * scale);
        uint32_t off = (uint32_t)(row * 128 + ((sl ^ (row & 7)) << 4));
        *reinterpret_cast<uint4*>(smem + off) = o;
    }
    __syncthreads();

    uint32_t qh[4][4];
    {
        int row = wq * 16 + (l & 15);
        uint32_t rbase = (uint32_t)(row * 128);
        int rx = row & 7;
        #pragma unroll
        for (int kb = 0; kb < 4; ++kb) {
            int s = kb * 2 + (l >> 4);
            ldm_x4(qh[kb], sb + rbase + (uint32_t)((s ^ rx) << 4));
        }
    }
    asm volatile("" :: "r"(qh[0][0]), "r"(qh[3][3]));
    __syncthreads();   // Q smem free; stages reuse it

    // ---- per-thread cp.async descriptors (3 granules / tile) ----
    const __half* kh_b  = g_kh  + (size_t)bh * TT * DHH;
    const __half* vth_b = g_vth + (size_t)bh * DHH * TT;
    const __half* vtl_b = g_vtl + (size_t)bh * DHH * TT;
    const __half* gb[3];
    int stp[3];
    uint32_t drel[3];
    #pragma unroll
    for (int it = 0; it < 3; ++it) {
        int id = it * 512 + tid;
        int part = id >> 9;              // 0:K 1:Vh 2:Vl
        int r = (id >> 3) & 63;
        int s2 = id & 7;
        if (part == 0)      { gb[it] = kh_b  + r * DHH + s2 * 8; stp[it] = 64 * DHH; }
        else if (part == 1) { gb[it] = vth_b + (size_t)r * TT + s2 * 8; stp[it] = 64; }
        else                { gb[it] = vtl_b + (size_t)r * TT + s2 * 8; stp[it] = 64; }
        drel[it] = (uint32_t)(part * 8192 + r * 128 + ((s2 ^ (r & 7)) << 4));
    }

    float o[8][4] = {};
    float m0 = -INFINITY, m1 = -INFINITY, ls0 = 0.f, ls1 = 0.f;
    const int ntiles = 4 * (qt + 1);

    // prologue: tiles 0,1
    #pragma unroll
    for (int pc = 0; pc < 2; ++pc) {
        const uint32_t sb2 = sb + pc * ASTG;
        #pragma unroll
        for (int it = 0; it < 3; ++it) cp16(sb2 + drel[it], gb[it] + pc * stp[it]);
        CP_COMMIT();
    }

    const int qr0 = q0 + wq * 16 + (l >> 2);
    const int qr1 = qr0 + 8;

    int stage = 0;
    for (int ti = 0; ti < ntiles; ++ti) {
        const int j0 = ti * 64;
        if (ti + 1 < ntiles) CP_WAIT1(); else CP_WAIT0();
        __syncthreads();
        if (ti + 2 < ntiles) {
            const int sn = (stage + 2 >= 3) ? stage - 1 : stage + 2;
            const uint32_t sb2 = sb + sn * ASTG;
            #pragma unroll
            for (int it = 0; it < 3; ++it) cp16(sb2 + drel[it], gb[it] + (ti + 2) * stp[it]);
            CP_COMMIT();
        }
        const uint32_t stK = sb + stage * ASTG;
        const uint32_t stVH = stK + 8192, stVL = stK + 16384;

        // ---- S = Q K^T (single pass) ----
        float s[8][4] = {};
        {
            int rbl = (l >> 4) * 8 + (l & 7);
            int sbit = (l >> 3) & 1;
            #pragma unroll
            for (int nbp = 0; nbp < 4; ++nbp) {
                int row = nbp * 16 + rbl;
                uint32_t rbase = (uint32_t)(row * 128);
                int rx = row & 7;
                #pragma unroll
                for (int kb = 0; kb < 4; ++kb) {
                    int sl = kb * 2 + sbit;
                    uint32_t off = rbase + (uint32_t)((sl ^ rx) << 4);
                    uint32_t bk4[4];
                    ldm_x4(bk4, stK + off);
                    mma16816(s[2 * nbp],     qh[kb], bk4);
                    mma16816(s[2 * nbp + 1], qh[kb], bk4 + 2);
                }
            }
        }

        // ---- causal mask (tiles overlapping the query block) ----
        if (j0 >= q0) {
            #pragma unroll
            for (int nb = 0; nb < 8; ++nb) {
                int k0i = j0 + nb * 8 + 2 * (l & 3);
                if (k0i     > qr0) s[nb][0] = -INFINITY;
                if (k0i + 1 > qr0) s[nb][1] = -INFINITY;
                if (k0i     > qr1) s[nb][2] = -INFINITY;
                if (k0i + 1 > qr1) s[nb][3] = -INFINITY;
            }
        }

        // ---- online softmax ----
        float mx0 = -INFINITY, mx1 = -INFINITY;
        #pragma unroll
        for (int nb = 0; nb < 8; ++nb) {
            mx0 = fmaxf(mx0, fmaxf(s[nb][0], s[nb][1]));
            mx1 = fmaxf(mx1, fmaxf(s[nb][2], s[nb][3]));
        }
        mx0 = fmaxf(mx0, __shfl_xor_sync(0xffffffffu, mx0, 1));
        mx0 = fmaxf(mx0, __shfl_xor_sync(0xffffffffu, mx0, 2));
        mx1 = fmaxf(mx1, __shfl_xor_sync(0xffffffffu, mx1, 1));
        mx1 = fmaxf(mx1, __shfl_xor_sync(0xffffffffu, mx1, 2));
        float nm0 = fmaxf(m0, mx0), nm1 = fmaxf(m1, mx1);
        float c0 = __expf(m0 - nm0), c1 = __expf(m1 - nm1);
        ls0 *= c0; ls1 *= c1;
        #pragma unroll
        for (int db = 0; db < 8; ++db) {
            o[db][0] *= c0; o[db][1] *= c0;
            o[db][2] *= c1; o[db][3] *= c1;
        }
        float r0 = 0.f, r1 = 0.f;
        #pragma unroll
        for (int nb = 0; nb < 8; ++nb) {
            s[nb][0] = __expf(s[nb][0] - nm0);
            s[nb][1] = __expf(s[nb][1] - nm0);
            s[nb][2] = __expf(s[nb][2] - nm1);
            s[nb][3] = __expf(s[nb][3] - nm1);
            r0 += s[nb][0] + s[nb][1];
            r1 += s[nb][2] + s[nb][3];
        }
        r0 += __shfl_xor_sync(0xffffffffu, r0, 1);
        r0 += __shfl_xor_sync(0xffffffffu, r0, 2);
        r1 += __shfl_xor_sync(0xffffffffu, r1, 1);
        r1 += __shfl_xor_sync(0xffffffffu, r1, 2);
        ls0 += r0; ls1 += r1;
        m0 = nm0; m1 = nm1;

        // ---- P -> fp16 A-fragments ----
        uint32_t pa[4][4];
        #pragma unroll
        for (int kp = 0; kp < 4; ++kp) {
            pa[kp][0] = pack_f16(s[2 * kp][0],     s[2 * kp][1]);
            pa[kp][1] = pack_f16(s[2 * kp][2],     s[2 * kp][3]);
            pa[kp][2] = pack_f16(s[2 * kp + 1][0], s[2 * kp + 1][1]);
            pa[kp][3] = pack_f16(s[2 * kp + 1][2], s[2 * kp + 1][3]);
        }

        // ---- O += P (Vh+Vl) ----
        {
            int rbl = (l >> 4) * 8 + (l & 7);
            int sbit = (l >> 3) & 1;
            #pragma unroll
            for (int dbp = 0; dbp < 4; ++dbp) {
                int row = dbp * 16 + rbl;
                uint32_t rbase = (uint32_t)(row * 128);
                int rx = row & 7;
                #pragma unroll
                for (int kp = 0; kp < 4; ++kp) {
                    int sl = kp * 2 + sbit;
                    uint32_t off = rbase + (uint32_t)((sl ^ rx) << 4);
                    uint32_t vh4[4], vl4[4];
                    ldm_x4(vh4, stVH + off);
                    ldm_x4(vl4, stVL + off);
                    mma16816(o[2 * dbp],     pa[kp], vh4);
                    mma16816(o[2 * dbp],     pa[kp], vl4);
                    mma16816(o[2 * dbp + 1], pa[kp], vh4 + 2);
                    mma16816(o[2 * dbp + 1], pa[kp], vl4 + 2);
                }
            }
        }
        stage = (stage + 1 == 3) ? 0 : stage + 1;
    }

    // ---- epilogue ----
    const float inv0 = 1.0f / ls0, inv1 = 1.0f / ls1;
    uint32_t* oh0 = (uint32_t*)(ath + ((size_t)(b * TT + qr0)) * CC + h * DHH);
    uint32_t* ol0 = (uint32_t*)(atl + ((size_t)(b * TT + qr0)) * CC + h * DHH);
    uint32_t* oh1 = (uint32_t*)(ath + ((size_t)(b * TT + qr1)) * CC + h * DHH);
    uint32_t* ol1 = (uint32_t*)(atl + ((size_t)(b * TT + qr1)) * CC + h * DHH);
    #pragma unroll
    for (int db = 0; db < 8; ++db) {
        int cidx = (db * 8 + 2 * (l & 3)) >> 1;
        uint32_t hp, lp;
        split2h(o[db][0] * inv0, o[db][1] * inv0, hp, lp);
        oh0[cidx] = hp; ol0[cidx] = lp;
        split2h(o[db][2] * inv1, o[db][3] * inv1, hp, lp);
        oh1[cidx] = hp; ol1[cidx] = lp;
    }
}

// ------------------------------- launch -------------------------------------
extern "C" void kernel_launch(void* const* d_in, const int* in_sizes, int n_in,
                              void* d_out, int out_size) {
    const float* x  = (const float*)d_in[0];
    const float* Wq = (const float*)d_in[1];
    const float* bq = (const float*)d_in[2];
    const float* Wk = (const float*)d_in[3];
    const float* bk = (const float*)d_in[4];
    const float* Wv = (const float*)d_in[5];
    const float* bv = (const float*)d_in[6];
    const float* Wo = (const float*)d_in[7];
    const float* bo = (const float*)d_in[8];
    float* out = (float*)d_out;

    cudaFuncSetAttribute(gemm_fp16x2, cudaFuncAttributeMaxDynamicSharedMemorySize, SMEM_GEMM);
    cudaFuncSetAttribute(attn_mma,    cudaFuncAttributeMaxDynamicSharedMemorySize, SMEM_ATTN);

    float *qkvp, *biasp;
    __half *xh, *xl, *wt, *wot, *ath, *atl;
    cudaGetSymbolAddress((void**)&xh, g_xh);
    cudaGetSymbolAddress((void**)&xl, g_xl);
    cudaGetSymbolAddress((void**)&wt, g_wt);
    cudaGetSymbolAddress((void**)&wot, g_wot);
    cudaGetSymbolAddress((void**)&biasp, g_bias);
    cudaGetSymbolAddress((void**)&qkvp, g_qkv);
    cudaGetSymbolAddress((void**)&ath, g_ath);
    cudaGetSymbolAddress((void**)&atl, g_atl);

    int n4 = MROWS * CC / 4;
    conv_split<<<n4 / 256, 256>>>((const float4*)x, (uint32_t*)xh, (uint32_t*)xl, n4);
    repack_qkv<<<NQKV, 256>>>(Wq, Wk, Wv, bq, bk, bv);
    repack_wo<<<CC, 256>>>(Wo);

    // Q,K thirds (n0 < 2048): 1-pass; V third: 2-pass
    gemm_fp16x2<<<dim3(MROWS / 128, NQKV / 128), 512, SMEM_GEMM>>>(
        xh, xl, wt, biasp, qkvp, NQKV, 2 * CC);

    conv_kv<<<dim3(TT / 64, BB * HH), 256>>>(qkvp);

    attn_mma<<<dim3(TT / QPC, BB * HH), 512, SMEM_ATTN>>>(qkvp, ath, atl);

    // output projection: all 2-pass
    gemm_fp16x2<<<dim3(MROWS / 128, CC / 128), 512, SMEM_GEMM>>>(
        ath, atl, wot, bo, out, CC, 0);
}

// round 10
// speedup vs baseline: 1.0798x; 1.0798x over previous
#include <cuda_runtime.h>
#include <cuda_fp16.h>
#include <math.h>
#include <stdint.h>

#define BB 4
#define TT 2048
#define CC 1024
#define HH 16
#define DHH 64
#define MROWS (BB*TT)     // 8192
#define NQKV (3*CC)       // 3072

// ------------------------------- scratch (no allocs allowed) ----------------
__device__ __half g_xh[(size_t)MROWS*CC];
__device__ __half g_xl[(size_t)MROWS*CC];
__device__ __half g_wt[(size_t)NQKV*CC];     // QKV weights, fp16, [N][K] (Wq pre-scaled by 1/32)
__device__ __half g_wot[(size_t)CC*CC];      // Wo^T, fp16, [N][K]
__device__ float  g_bias[NQKV];              // bq pre-scaled by 1/32
__device__ __half g_qh [(size_t)MROWS*CC];   // Q fp16 (scaled) [m][c]
__device__ __half g_kh [(size_t)BB*HH*TT*DHH];   // K fp16 [bh][t][d]
__device__ __half g_vth[(size_t)BB*HH*DHH*TT];   // V hi fp16 [bh][d][t]
__device__ __half g_vtl[(size_t)BB*HH*DHH*TT];   // V lo fp16 [bh][d][t]
__device__ __half g_ath[(size_t)MROWS*CC];
__device__ __half g_atl[(size_t)MROWS*CC];

// ------------------------------- PTX helpers --------------------------------
__device__ __forceinline__ uint32_t smem_u32(const void* p) {
    uint32_t a;
    asm("{ .reg .u64 t; cvta.to.shared.u64 t, %1; cvt.u32.u64 %0, t; }" : "=r"(a) : "l"(p));
    return a;
}
__device__ __forceinline__ void cp16(uint32_t dst, const void* src) {
    asm volatile("cp.async.cg.shared.global [%0], [%1], 16;" :: "r"(dst), "l"(src));
}
#define CP_COMMIT() asm volatile("cp.async.commit_group;" ::: "memory")
#define CP_WAIT2()  asm volatile("cp.async.wait_group 2;" ::: "memory")
#define CP_WAIT1()  asm volatile("cp.async.wait_group 1;" ::: "memory")
#define CP_WAIT0()  asm volatile("cp.async.wait_group 0;" ::: "memory")
__device__ __forceinline__ void ldm_x4(uint32_t* r, uint32_t addr) {
    asm volatile("ldmatrix.sync.aligned.m8n8.x4.shared.b16 {%0,%1,%2,%3}, [%4];"
                 : "=r"(r[0]), "=r"(r[1]), "=r"(r[2]), "=r"(r[3]) : "r"(addr));
}
__device__ __forceinline__ void mma16816(float* d, const uint32_t* a, const uint32_t* b) {
    asm volatile(
        "mma.sync.aligned.m16n8k16.row.col.f32.f16.f16.f32 "
        "{%0,%1,%2,%3}, {%4,%5,%6,%7}, {%8,%9}, {%0,%1,%2,%3};"
        : "+f"(d[0]), "+f"(d[1]), "+f"(d[2]), "+f"(d[3])
        : "r"(a[0]), "r"(a[1]), "r"(a[2]), "r"(a[3]), "r"(b[0]), "r"(b[1]));
}
__device__ __forceinline__ uint32_t pack_f16(float v0, float v1) {
    uint32_t r;
    asm("cvt.rn.f16x2.f32 %0, %1, %2;" : "=r"(r) : "f"(v1), "f"(v0));
    return r;
}
__device__ __forceinline__ void split2h(float v0, float v1, uint32_t& hp, uint32_t& lp) {
    hp = pack_f16(v0, v1);
    __half2 h = *reinterpret_cast<__half2*>(&hp);
    float2 f = __half22float2(h);
    lp = pack_f16(v0 - f.x, v1 - f.y);
}

// ------------------------------- conversion ---------------------------------
__global__ __launch_bounds__(256) void conv_split(
    const float4* __restrict__ src, uint32_t* __restrict__ hi,
    uint32_t* __restrict__ lo, int n4)
{
    int i = blockIdx.x * blockDim.x + threadIdx.x;
    if (i >= n4) return;
    float4 v = src[i];
    uint32_t h0, l0, h1, l1;
    split2h(v.x, v.y, h0, l0);
    split2h(v.z, v.w, h1, l1);
    hi[2*i] = h0; hi[2*i+1] = h1;
    lo[2*i] = l0; lo[2*i+1] = l1;
}

__global__ __launch_bounds__(256) void repack_qkv(
    const float* __restrict__ Wq, const float* __restrict__ Wk, const float* __restrict__ Wv,
    const float* __restrict__ bq, const float* __restrict__ bk, const float* __restrict__ bv)
{
    int n = blockIdx.x;                    // 0..3071
    int p = n >> 10, w = n & 1023;
    int h = w >> 6, d = w & 63;
    const float* W = (p == 0) ? Wq : (p == 1) ? Wk : Wv;
    const float* bsrc = (p == 0) ? bq : (p == 1) ? bk : bv;
    const float sc = (p == 0) ? 0.03125f : 1.0f;   // fold attention scale into Q proj
    for (int c = threadIdx.x; c < CC; c += 256)
        g_wt[(size_t)n * CC + c] = __float2half_rn(W[((size_t)h * CC + c) * DHH + d] * sc);
    if (threadIdx.x == 0) g_bias[n] = bsrc[w] * sc;
}

__global__ __launch_bounds__(256) void repack_wo(const float* __restrict__ Wo)
{
    int n = blockIdx.x;
    for (int c = threadIdx.x; c < CC; c += 256)
        g_wot[(size_t)n * CC + c] = __float2half_rn(Wo[(size_t)c * CC + n]);
}

// ------------------------------- mma.sync GEMM (3-stage) --------------------
// mode 0: C[m,n] = (Ah [+Al]) @ B^T + bias  (fp32 out, oproj)
// mode 1: fused QKV epilogue -> g_qh / g_kh / g_vth,g_vtl
#define KCH 64
#define NCH (CC / KCH)        // 16 chunks
#define TILEB 16384           // 128 rows x 128 B
#define GST (3 * TILEB)       // 48 KB / stage
#define SMEM_GEMM (3 * GST)   // 144 KB

__global__ void __launch_bounds__(256, 1) gemm_fp16x2(
    const __half* __restrict__ Ah, const __half* __restrict__ Al,
    const __half* __restrict__ B,
    const float* __restrict__ bias, float* __restrict__ C, int ldc,
    int vstart, int mode)
{
    extern __shared__ char dsm[];
    const uint32_t sbase = smem_u32(dsm);
    const int tid = threadIdx.x;
    const int l   = tid & 31;
    const int wid = tid >> 5;
    const int wm  = wid & 1;
    const int wn  = wid >> 1;
    const int m0  = blockIdx.x * 128;
    const int n0  = blockIdx.y * 128;
    const bool twoPass = (n0 >= vstart);

    const __half* gptr[12];
    uint32_t srel[12];
    bool gact[12];
    {
        const __half* bases[3] = {Ah, Al, B};
        #pragma unroll
        for (int it = 0; it < 12; ++it) {
            int g = it * 256 + tid;
            int tile = g >> 10;
            int r = (g >> 3) & 127;
            int slot = g & 7;
            int row0 = (tile < 2) ? m0 : n0;
            gptr[it] = bases[tile] + (size_t)(row0 + r) * CC + slot * 8;
            srel[it] = tile * TILEB + r * 128 + ((slot ^ (r & 7)) << 4);
            gact[it] = (tile != 1) || twoPass;
        }
    }

    const int hA = l >> 4;
    uint32_t aBase[4]; int ax[4];
    #pragma unroll
    for (int i = 0; i < 4; ++i) {
        int rr = wm * 64 + (l & 15) + i * 16;
        aBase[i] = (uint32_t)(rr * 128); ax[i] = rr & 7;
    }
    const int hB = (l >> 3) & 1;
    uint32_t bBase[2]; int bx[2];
    #pragma unroll
    for (int j = 0; j < 2; ++j) {
        int rr = wn * 32 + ((l & 7) | ((l >> 4) << 3)) + j * 16;
        bBase[j] = (uint32_t)(rr * 128); bx[j] = rr & 7;
    }

    float acc[4][4][4] = {};

    // prologue: stages 0,1
    #pragma unroll
    for (int pc = 0; pc < 2; ++pc) {
        const uint32_t sb2 = sbase + pc * GST;
        const int kadv = pc * KCH;
        #pragma unroll
        for (int it = 0; it < 12; ++it)
            if (gact[it]) cp16(sb2 + srel[it], gptr[it] + kadv);
        CP_COMMIT();
    }

    int stage = 0;
    for (int c = 0; c < NCH; ++c) {
        if (c + 1 < NCH) CP_WAIT1(); else CP_WAIT0();
        __syncthreads();
        if (c + 2 < NCH) {
            const int sn = (stage + 2 >= 3) ? stage - 1 : stage + 2;
            const uint32_t sb2 = sbase + sn * GST;
            const int kadv = (c + 2) * KCH;
            #pragma unroll
            for (int it = 0; it < 12; ++it)
                if (gact[it]) cp16(sb2 + srel[it], gptr[it] + kadv);
            CP_COMMIT();
        }

        const uint32_t st = sbase + stage * GST;
        const uint32_t sAh = st, sAl = st + TILEB, sB = st + 2 * TILEB;
        #pragma unroll
        for (int ks = 0; ks < 4; ++ks) {
            const int slA = ks * 2 + hA;
            const int slB = ks * 2 + hB;
            uint32_t ah[4][4], al_[4][4], bf[4][2];
            #pragma unroll
            for (int i = 0; i < 4; ++i) {
                uint32_t off = aBase[i] + (uint32_t)((slA ^ ax[i]) << 4);
                ldm_x4(ah[i], sAh + off);
                if (twoPass) ldm_x4(al_[i], sAl + off);
            }
            #pragma unroll
            for (int j = 0; j < 2; ++j) {
                uint32_t t[4];
                ldm_x4(t, sB + bBase[j] + (uint32_t)((slB ^ bx[j]) << 4));
                bf[2*j][0] = t[0]; bf[2*j][1] = t[1];
                bf[2*j+1][0] = t[2]; bf[2*j+1][1] = t[3];
            }
            #pragma unroll
            for (int i = 0; i < 4; ++i)
                #pragma unroll
                for (int j = 0; j < 4; ++j) {
                    mma16816(acc[i][j], ah[i], bf[j]);
                    if (twoPass) mma16816(acc[i][j], al_[i], bf[j]);
                }
        }
        stage = (stage + 1 == 3) ? 0 : stage + 1;
    }

    // ------------------------------ epilogue ------------------------------
    if (mode == 0) {
        #pragma unroll
        for (int i = 0; i < 4; ++i) {
            const int m = m0 + wm * 64 + i * 16 + (l >> 2);
            #pragma unroll
            for (int j = 0; j < 4; ++j) {
                const int n = n0 + wn * 32 + j * 8 + 2 * (l & 3);
                const float b0 = bias[n], b1 = bias[n + 1];
                float2 v0 = { acc[i][j][0] + b0, acc[i][j][1] + b1 };
                float2 v1 = { acc[i][j][2] + b0, acc[i][j][3] + b1 };
                *reinterpret_cast<float2*>(&C[(size_t)m * ldc + n]) = v0;
                *reinterpret_cast<float2*>(&C[(size_t)(m + 8) * ldc + n]) = v1;
            }
        }
    } else if (n0 < CC) {
        // Q: fp16 (already scaled), [m][n]
        uint32_t* qh32 = reinterpret_cast<uint32_t*>(g_qh);
        #pragma unroll
        for (int i = 0; i < 4; ++i) {
            const int m = m0 + wm * 64 + i * 16 + (l >> 2);
            #pragma unroll
            for (int j = 0; j < 4; ++j) {
                const int n = n0 + wn * 32 + j * 8 + 2 * (l & 3);
                const float b0 = bias[n], b1 = bias[n + 1];
                size_t off = (size_t)m * CC + n;
                qh32[off >> 1] = pack_f16(acc[i][j][0] + b0, acc[i][j][1] + b1);
                qh32[(off + (size_t)8 * CC) >> 1] = pack_f16(acc[i][j][2] + b0, acc[i][j][3] + b1);
            }
        }
    } else if (n0 < 2 * CC) {
        // K: fp16 [bh][t][d]
        uint32_t* kh32 = reinterpret_cast<uint32_t*>(g_kh);
        #pragma unroll
        for (int i = 0; i < 4; ++i) {
            const int m = m0 + wm * 64 + i * 16 + (l >> 2);
            const int bsel = m >> 11, t = m & 2047;
            #pragma unroll
            for (int j = 0; j < 4; ++j) {
                const int n = n0 + wn * 32 + j * 8 + 2 * (l & 3);
                const int h = (n >> 6) & 15, d = n & 63;
                const float b0 = bias[n], b1 = bias[n + 1];
                size_t off = (((size_t)(bsel * HH + h) * TT + t) * DHH + d);
                kh32[off >> 1] = pack_f16(acc[i][j][0] + b0, acc[i][j][1] + b1);
                kh32[(off + (size_t)8 * DHH) >> 1] = pack_f16(acc[i][j][2] + b0, acc[i][j][3] + b1);
            }
        }
    } else {
        // V: fp16 hi/lo transposed [bh][d][t]
        #pragma unroll
        for (int i = 0; i < 4; ++i) {
            const int m = m0 + wm * 64 + i * 16 + (l >> 2);
            const int bsel = m >> 11, t = m & 2047;
            #pragma unroll
            for (int j = 0; j < 4; ++j) {
                const int n = n0 + wn * 32 + j * 8 + 2 * (l & 3);
                const int h = (n >> 6) & 15, d = n & 63;
                const float b0 = bias[n], b1 = bias[n + 1];
                size_t base = ((size_t)(bsel * HH + h) * DHH + d) * TT + t;
                float v0 = acc[i][j][0] + b0, v1 = acc[i][j][1] + b1;
                float v2 = acc[i][j][2] + b0, v3 = acc[i][j][3] + b1;
                __half h0 = __float2half_rn(v0);
                __half h1 = __float2half_rn(v1);
                __half h2 = __float2half_rn(v2);
                __half h3 = __float2half_rn(v3);
                g_vth[base]          = h0;
                g_vth[base + TT]     = h1;
                g_vth[base + 8]      = h2;
                g_vth[base + TT + 8] = h3;
                g_vtl[base]          = __float2half_rn(v0 - __half2float(h0));
                g_vtl[base + TT]     = __float2half_rn(v1 - __half2float(h1));
                g_vtl[base + 8]      = __float2half_rn(v2 - __half2float(h2));
                g_vtl[base + TT + 8] = __float2half_rn(v3 - __half2float(h3));
            }
        }
    }
}

// ------------------------------- mma flash attention (3-stage cp.async) -----
// stage (24KB): K[64 keys][128B] @0, Vth[64 dims][128B] @8192, Vtl @16384
// Q fp16 region: dedicated 16KB at 3*ASTG (no overlap with stages -> full overlap)
#define ASTG 24576
#define QOFF (3 * ASTG)               // 73728
#define SMEM_ATTN (QOFF + 16384)      // 90112

__global__ void __launch_bounds__(256, 1) attn_mma(
    __half* __restrict__ ath, __half* __restrict__ atl)
{
    extern __shared__ char smem[];
    const uint32_t sb = smem_u32(smem);
    const int tid = threadIdx.x;
    const int l   = tid & 31;
    const int wq  = tid >> 5;
    const int bh  = blockIdx.y;
    const int b   = bh >> 4, h = bh & 15;
    const int qt  = gridDim.x - 1 - blockIdx.x;
    const int q0  = qt * 128;

    // ---- Q cp.async (fp16, pre-scaled) group 0 ----
    const __half* qg = g_qh + ((size_t)(b * TT + q0)) * CC + h * DHH;
    #pragma unroll
    for (int it = 0; it < 4; ++it) {
        int id = it * 256 + tid;
        int row = id >> 3, sl = id & 7;
        cp16(sb + QOFF + (uint32_t)(row * 128 + ((sl ^ (row & 7)) << 4)),
             qg + (size_t)row * CC + sl * 8);
    }
    CP_COMMIT();

    // ---- per-thread KV cp.async descriptors (6 granules / tile) ----
    const __half* kh_b  = g_kh  + (size_t)bh * TT * DHH;
    const __half* vth_b = g_vth + (size_t)bh * DHH * TT;
    const __half* vtl_b = g_vtl + (size_t)bh * DHH * TT;
    const __half* gb[6];
    int stp[6];
    uint32_t drel[6];
    #pragma unroll
    for (int it = 0; it < 6; ++it) {
        int id = it * 256 + tid;
        int part = id >> 9;              // 0:K 1:Vh 2:Vl
        int r = (id >> 3) & 63;
        int s2 = id & 7;
        if (part == 0)      { gb[it] = kh_b  + r * DHH + s2 * 8; stp[it] = 64 * DHH; }
        else if (part == 1) { gb[it] = vth_b + (size_t)r * TT + s2 * 8; stp[it] = 64; }
        else                { gb[it] = vtl_b + (size_t)r * TT + s2 * 8; stp[it] = 64; }
        drel[it] = (uint32_t)(part * 8192 + r * 128 + ((s2 ^ (r & 7)) << 4));
    }

    const int ntiles = 2 * (qt + 1);

    // KV prologue: tiles 0,1 (groups 1,2) — overlaps with Q load
    #pragma unroll
    for (int pc = 0; pc < 2; ++pc) {
        const uint32_t sb2 = sb + pc * ASTG;
        #pragma unroll
        for (int it = 0; it < 6; ++it) cp16(sb2 + drel[it], gb[it] + pc * stp[it]);
        CP_COMMIT();
    }

    // wait for Q (2 groups may remain pending), then build Q fragments
    CP_WAIT2();
    __syncthreads();
    uint32_t qh[4][4];
    {
        int row = wq * 16 + (l & 15);
        uint32_t rbase = (uint32_t)(QOFF + row * 128);
        int rx = row & 7;
        #pragma unroll
        for (int kb = 0; kb < 4; ++kb) {
            int s = kb * 2 + (l >> 4);
            ldm_x4(qh[kb], sb + rbase + (uint32_t)((s ^ rx) << 4));
        }
    }

    float o[8][4] = {};
    float m0 = -INFINITY, m1 = -INFINITY, ls0 = 0.f, ls1 = 0.f;
    const int qr0 = q0 + wq * 16 + (l >> 2);
    const int qr1 = qr0 + 8;

    int stage = 0;
    for (int ti = 0; ti < ntiles; ++ti) {
        const int j0 = ti * 64;
        if (ti + 1 < ntiles) CP_WAIT1(); else CP_WAIT0();
        __syncthreads();
        if (ti + 2 < ntiles) {
            const int sn = (stage + 2 >= 3) ? stage - 1 : stage + 2;
            const uint32_t sb2 = sb + sn * ASTG;
            #pragma unroll
            for (int it = 0; it < 6; ++it) cp16(sb2 + drel[it], gb[it] + (ti + 2) * stp[it]);
            CP_COMMIT();
        }
        const uint32_t stK = sb + stage * ASTG;
        const uint32_t stVH = stK + 8192, stVL = stK + 16384;

        // ---- S = Q K^T (single pass) ----
        float s[8][4] = {};
        {
            int rbl = (l >> 4) * 8 + (l & 7);
            int sbit = (l >> 3) & 1;
            #pragma unroll
            for (int nbp = 0; nbp < 4; ++nbp) {
                int row = nbp * 16 + rbl;
                uint32_t rbase = (uint32_t)(row * 128);
                int rx = row & 7;
                #pragma unroll
                for (int kb = 0; kb < 4; ++kb) {
                    int sl = kb * 2 + sbit;
                    uint32_t off = rbase + (uint32_t)((sl ^ rx) << 4);
                    uint32_t bk4[4];
                    ldm_x4(bk4, stK + off);
                    mma16816(s[2 * nbp],     qh[kb], bk4);
                    mma16816(s[2 * nbp + 1], qh[kb], bk4 + 2);
                }
            }
        }

        // ---- causal mask ----
        if (j0 >= q0) {
            #pragma unroll
            for (int nb = 0; nb < 8; ++nb) {
                int k0i = j0 + nb * 8 + 2 * (l & 3);
                if (k0i     > qr0) s[nb][0] = -INFINITY;
                if (k0i + 1 > qr0) s[nb][1] = -INFINITY;
                if (k0i     > qr1) s[nb][2] = -INFINITY;
                if (k0i + 1 > qr1) s[nb][3] = -INFINITY;
            }
        }

        // ---- online softmax ----
        float mx0 = -INFINITY, mx1 = -INFINITY;
        #pragma unroll
        for (int nb = 0; nb < 8; ++nb) {
            mx0 = fmaxf(mx0, fmaxf(s[nb][0], s[nb][1]));
            mx1 = fmaxf(mx1, fmaxf(s[nb][2], s[nb][3]));
        }
        mx0 = fmaxf(mx0, __shfl_xor_sync(0xffffffffu, mx0, 1));
        mx0 = fmaxf(mx0, __shfl_xor_sync(0xffffffffu, mx0, 2));
        mx1 = fmaxf(mx1, __shfl_xor_sync(0xffffffffu, mx1, 1));
        mx1 = fmaxf(mx1, __shfl_xor_sync(0xffffffffu, mx1, 2));
        float nm0 = fmaxf(m0, mx0), nm1 = fmaxf(m1, mx1);
        float c0 = __expf(m0 - nm0), c1 = __expf(m1 - nm1);
        ls0 *= c0; ls1 *= c1;
        #pragma unroll
        for (int db = 0; db < 8; ++db) {
            o[db][0] *= c0; o[db][1] *= c0;
            o[db][2] *= c1; o[db][3] *= c1;
        }
        float r0 = 0.f, r1 = 0.f;
        #pragma unroll
        for (int nb = 0; nb < 8; ++nb) {
            s[nb][0] = __expf(s[nb][0] - nm0);
            s[nb][1] = __expf(s[nb][1] - nm0);
            s[nb][2] = __expf(s[nb][2] - nm1);
            s[nb][3] = __expf(s[nb][3] - nm1);
            r0 += s[nb][0] + s[nb][1];
            r1 += s[nb][2] + s[nb][3];
        }
        r0 += __shfl_xor_sync(0xffffffffu, r0, 1);
        r0 += __shfl_xor_sync(0xffffffffu, r0, 2);
        r1 += __shfl_xor_sync(0xffffffffu, r1, 1);
        r1 += __shfl_xor_sync(0xffffffffu, r1, 2);
        ls0 += r0; ls1 += r1;
        m0 = nm0; m1 = nm1;

        // ---- P -> fp16 A-fragments ----
        uint32_t pa[4][4];
        #pragma unroll
        for (int kp = 0; kp < 4; ++kp) {
            pa[kp][0] = pack_f16(s[2 * kp][0],     s[2 * kp][1]);
            pa[kp][1] = pack_f16(s[2 * kp][2],     s[2 * kp][3]);
            pa[kp][2] = pack_f16(s[2 * kp + 1][0], s[2 * kp + 1][1]);
            pa[kp][3] = pack_f16(s[2 * kp + 1][2], s[2 * kp + 1][3]);
        }

        // ---- O += P (Vh+Vl) ----
        {
            int rbl = (l >> 4) * 8 + (l & 7);
            int sbit = (l >> 3) & 1;
            #pragma unroll
            for (int dbp = 0; dbp < 4; ++dbp) {
                int row = dbp * 16 + rbl;
                uint32_t rbase = (uint32_t)(row * 128);
                int rx = row & 7;
                #pragma unroll
                for (int kp = 0; kp < 4; ++kp) {
                    int sl = kp * 2 + sbit;
                    uint32_t off = rbase + (uint32_t)((sl ^ rx) << 4);
                    uint32_t vh4[4], vl4[4];
                    ldm_x4(vh4, stVH + off);
                    ldm_x4(vl4, stVL + off);
                    mma16816(o[2 * dbp],     pa[kp], vh4);
                    mma16816(o[2 * dbp],     pa[kp], vl4);
                    mma16816(o[2 * dbp + 1], pa[kp], vh4 + 2);
                    mma16816(o[2 * dbp + 1], pa[kp], vl4 + 2);
                }
            }
        }
        stage = (stage + 1 == 3) ? 0 : stage + 1;
    }

    // ---- epilogue ----
    const float inv0 = 1.0f / ls0, inv1 = 1.0f / ls1;
    uint32_t* oh0 = (uint32_t*)(ath + ((size_t)(b * TT + qr0)) * CC + h * DHH);
    uint32_t* ol0 = (uint32_t*)(atl + ((size_t)(b * TT + qr0)) * CC + h * DHH);
    uint32_t* oh1 = (uint32_t*)(ath + ((size_t)(b * TT + qr1)) * CC + h * DHH);
    uint32_t* ol1 = (uint32_t*)(atl + ((size_t)(b * TT + qr1)) * CC + h * DHH);
    #pragma unroll
    for (int db = 0; db < 8; ++db) {
        int cidx = (db * 8 + 2 * (l & 3)) >> 1;
        uint32_t hp, lp;
        split2h(o[db][0] * inv0, o[db][1] * inv0, hp, lp);
        oh0[cidx] = hp; ol0[cidx] = lp;
        split2h(o[db][2] * inv1, o[db][3] * inv1, hp, lp);
        oh1[cidx] = hp; ol1[cidx] = lp;
    }
}

// ------------------------------- launch -------------------------------------
extern "C" void kernel_launch(void* const* d_in, const int* in_sizes, int n_in,
                              void* d_out, int out_size) {
    const float* x  = (const float*)d_in[0];
    const float* Wq = (const float*)d_in[1];
    const float* bq = (const float*)d_in[2];
    const float* Wk = (const float*)d_in[3];
    const float* bk = (const float*)d_in[4];
    const float* Wv = (const float*)d_in[5];
    const float* bv = (const float*)d_in[6];
    const float* Wo = (const float*)d_in[7];
    const float* bo = (const float*)d_in[8];
    float* out = (float*)d_out;

    cudaFuncSetAttribute(gemm_fp16x2, cudaFuncAttributeMaxDynamicSharedMemorySize, SMEM_GEMM);
    cudaFuncSetAttribute(attn_mma,    cudaFuncAttributeMaxDynamicSharedMemorySize, SMEM_ATTN);

    float *biasp;
    __half *xh, *xl, *wt, *wot, *ath, *atl;
    cudaGetSymbolAddress((void**)&xh, g_xh);
    cudaGetSymbolAddress((void**)&xl, g_xl);
    cudaGetSymbolAddress((void**)&wt, g_wt);
    cudaGetSymbolAddress((void**)&wot, g_wot);
    cudaGetSymbolAddress((void**)&biasp, g_bias);
    cudaGetSymbolAddress((void**)&ath, g_ath);
    cudaGetSymbolAddress((void**)&atl, g_atl);

    int n4 = MROWS * CC / 4;
    conv_split<<<n4 / 256, 256>>>((const float4*)x, (uint32_t*)xh, (uint32_t*)xl, n4);
    repack_qkv<<<NQKV, 256>>>(Wq, Wk, Wv, bq, bk, bv);
    repack_wo<<<CC, 256>>>(Wo);

    // fused QKV: Q,K thirds 1-pass; V third 2-pass; epilogue emits fp16 Q/K/V directly
    gemm_fp16x2<<<dim3(MROWS / 128, NQKV / 128), 256, SMEM_GEMM>>>(
        xh, xl, wt, biasp, nullptr, 0, 2 * CC, 1);

    attn_mma<<<dim3(TT / 128, BB * HH), 256, SMEM_ATTN>>>(ath, atl);

    // output projection: all 2-pass, fp32 out
    gemm_fp16x2<<<dim3(MROWS / 128, CC / 128), 256, SMEM_GEMM>>>(
        ath, atl, wot, bo, out, CC, 0, 0);
}

// round 11
// speedup vs baseline: 1.1942x; 1.1059x over previous
#include <cuda_runtime.h>
#include <cuda_fp16.h>
#include <math.h>
#include <stdint.h>

#define BB 4
#define TT 2048
#define CC 1024
#define HH 16
#define DHH 64
#define MROWS (BB*TT)     // 8192
#define NQKV (3*CC)       // 3072

// ------------------------------- scratch (no allocs allowed) ----------------
__device__ __half g_xh[(size_t)MROWS*CC];
__device__ __half g_xl[(size_t)MROWS*CC];
__device__ __half g_wt[(size_t)NQKV*CC];     // QKV weights fp16 [N][K] (Wq pre-scaled)
__device__ __half g_wot[(size_t)CC*CC];      // Wo^T fp16 [N][K]
__device__ float  g_bias[NQKV];              // bq pre-scaled
__device__ __half g_qh [(size_t)MROWS*CC];   // Q fp16 (scaled) [m][c]
__device__ __half g_kh [(size_t)BB*HH*TT*DHH];   // K fp16 [bh][t][d]
__device__ __half g_vth[(size_t)BB*HH*DHH*TT];   // V hi fp16 [bh][d][t]
__device__ __half g_vtl[(size_t)BB*HH*DHH*TT];   // V lo fp16 [bh][d][t]
__device__ __half g_ath[(size_t)MROWS*CC];
__device__ __half g_atl[(size_t)MROWS*CC];

// ------------------------------- PTX helpers --------------------------------
__device__ __forceinline__ uint32_t smem_u32(const void* p) {
    uint32_t a;
    asm("{ .reg .u64 t; cvta.to.shared.u64 t, %1; cvt.u32.u64 %0, t; }" : "=r"(a) : "l"(p));
    return a;
}
__device__ __forceinline__ void cp16(uint32_t dst, const void* src) {
    asm volatile("cp.async.cg.shared.global [%0], [%1], 16;" :: "r"(dst), "l"(src));
}
#define CP_COMMIT() asm volatile("cp.async.commit_group;" ::: "memory")
#define CP_WAIT2()  asm volatile("cp.async.wait_group 2;" ::: "memory")
#define CP_WAIT1()  asm volatile("cp.async.wait_group 1;" ::: "memory")
#define CP_WAIT0()  asm volatile("cp.async.wait_group 0;" ::: "memory")
__device__ __forceinline__ void ldm_x4(uint32_t* r, uint32_t addr) {
    asm volatile("ldmatrix.sync.aligned.m8n8.x4.shared.b16 {%0,%1,%2,%3}, [%4];"
                 : "=r"(r[0]), "=r"(r[1]), "=r"(r[2]), "=r"(r[3]) : "r"(addr));
}
__device__ __forceinline__ void mma16816(float* d, const uint32_t* a, const uint32_t* b) {
    asm volatile(
        "mma.sync.aligned.m16n8k16.row.col.f32.f16.f16.f32 "
        "{%0,%1,%2,%3}, {%4,%5,%6,%7}, {%8,%9}, {%0,%1,%2,%3};"
        : "+f"(d[0]), "+f"(d[1]), "+f"(d[2]), "+f"(d[3])
        : "r"(a[0]), "r"(a[1]), "r"(a[2]), "r"(a[3]), "r"(b[0]), "r"(b[1]));
}
__device__ __forceinline__ uint32_t pack_f16(float v0, float v1) {
    uint32_t r;
    asm("cvt.rn.f16x2.f32 %0, %1, %2;" : "=r"(r) : "f"(v1), "f"(v0));
    return r;
}
__device__ __forceinline__ void split2h(float v0, float v1, uint32_t& hp, uint32_t& lp) {
    hp = pack_f16(v0, v1);
    __half2 h = *reinterpret_cast<__half2*>(&hp);
    float2 f = __half22float2(h);
    lp = pack_f16(v0 - f.x, v1 - f.y);
}

// ------------------------------- conversion ---------------------------------
__global__ __launch_bounds__(256) void conv_split(
    const float4* __restrict__ src, uint32_t* __restrict__ hi,
    uint32_t* __restrict__ lo, int n4)
{
    int i = blockIdx.x * blockDim.x + threadIdx.x;
    if (i >= n4) return;
    float4 v = src[i];
    uint32_t h0, l0, h1, l1;
    split2h(v.x, v.y, h0, l0);
    split2h(v.z, v.w, h1, l1);
    hi[2*i] = h0; hi[2*i+1] = h1;
    lo[2*i] = l0; lo[2*i+1] = l1;
}

__global__ __launch_bounds__(256) void repack_qkv(
    const float* __restrict__ Wq, const float* __restrict__ Wk, const float* __restrict__ Wv,
    const float* __restrict__ bq, const float* __restrict__ bk, const float* __restrict__ bv)
{
    int n = blockIdx.x;
    int p = n >> 10, w = n & 1023;
    int h = w >> 6, d = w & 63;
    const float* W = (p == 0) ? Wq : (p == 1) ? Wk : Wv;
    const float* bsrc = (p == 0) ? bq : (p == 1) ? bk : bv;
    const float sc = (p == 0) ? 0.03125f : 1.0f;
    for (int c = threadIdx.x; c < CC; c += 256)
        g_wt[(size_t)n * CC + c] = __float2half_rn(W[((size_t)h * CC + c) * DHH + d] * sc);
    if (threadIdx.x == 0) g_bias[n] = bsrc[w] * sc;
}

__global__ __launch_bounds__(256) void repack_wo(const float* __restrict__ Wo)
{
    int n = blockIdx.x;
    for (int c = threadIdx.x; c < CC; c += 256)
        g_wot[(size_t)n * CC + c] = __float2half_rn(Wo[(size_t)c * CC + n]);
}

// ------------------- gemm_qk: 1-pass wide-N (128x256), Q/K only -------------
#define KCH 64
#define NCH (CC / KCH)        // 16
#define QK_AT 16384           // Ah tile: 128 x 128B
#define QK_BT 32768           // B tile: 256 x 128B
#define QK_ST (QK_AT + QK_BT) // 49152
#define SMEM_QK (2 * QK_ST)   // 98304

__global__ void __launch_bounds__(256, 1) gemm_qk(
    const __half* __restrict__ Ah, const __half* __restrict__ B,
    const float* __restrict__ bias)
{
    extern __shared__ char dsm[];
    const uint32_t sbase = smem_u32(dsm);
    const int tid = threadIdx.x;
    const int l   = tid & 31;
    const int wid = tid >> 5;
    const int wm  = wid & 1;        // 2 m-blocks of 64
    const int wn  = wid >> 1;       // 4 n-blocks of 64
    const int m0  = blockIdx.x * 128;
    const int n0  = blockIdx.y * 256;

    // cp.async granules: Ah 1024 + B 2048 = 3072; 12 per thread
    uint32_t goff[12];   // byte offset from tile base pointer
    uint32_t srel[12];
    #pragma unroll
    for (int it = 0; it < 12; ++it) {
        int g = it * 256 + tid;
        if (g < 1024) {
            int r = g >> 3, slot = g & 7;
            goff[it] = (uint32_t)(((m0 + r) * CC + slot * 8) * 2);
            srel[it] = (uint32_t)(r * 128 + ((slot ^ (r & 7)) << 4));
        } else {
            int gb = g - 1024;
            int r = gb >> 3, slot = gb & 7;
            goff[it] = (uint32_t)(((n0 + r) * CC + slot * 8) * 2);
            srel[it] = (uint32_t)(QK_AT + r * 128 + ((slot ^ (r & 7)) << 4));
        }
    }
    const char* aB = (const char*)Ah;
    const char* bB = (const char*)B;

    const int hA = l >> 4;
    uint32_t aBase[4]; int ax[4];
    #pragma unroll
    for (int i = 0; i < 4; ++i) {
        int rr = wm * 64 + (l & 15) + i * 16;
        aBase[i] = (uint32_t)(rr * 128); ax[i] = rr & 7;
    }
    const int hB = (l >> 3) & 1;
    uint32_t bBase[4]; int bx[4];
    #pragma unroll
    for (int jj = 0; jj < 4; ++jj) {
        int rr = wn * 64 + ((l & 7) | ((l >> 4) << 3)) + jj * 16;
        bBase[jj] = (uint32_t)(rr * 128); bx[jj] = rr & 7;
    }

    float acc[4][8][4] = {};

    // prologue: chunk 0 -> stage 0
    #pragma unroll
    for (int it = 0; it < 12; ++it)
        cp16(sbase + srel[it], (it * 256 + tid < 1024 ? aB : bB) + goff[it]);
    CP_COMMIT();

    for (int c = 0; c < NCH; ++c) {
        if (c + 1 < NCH) {
            const uint32_t sb2 = sbase + ((c + 1) & 1) * QK_ST;
            const uint32_t kb = (uint32_t)((c + 1) * KCH * 2);
            #pragma unroll
            for (int it = 0; it < 12; ++it)
                cp16(sb2 + srel[it], (it * 256 + tid < 1024 ? aB : bB) + goff[it] + kb);
            CP_COMMIT();
            CP_WAIT1();
        } else {
            CP_WAIT0();
        }
        __syncthreads();

        const uint32_t st = sbase + (c & 1) * QK_ST;
        const uint32_t sAh = st, sB = st + QK_AT;
        #pragma unroll
        for (int ks = 0; ks < 4; ++ks) {
            const int slA = ks * 2 + hA;
            const int slB = ks * 2 + hB;
            uint32_t ah[4][4], bf[8][2];
            #pragma unroll
            for (int i = 0; i < 4; ++i)
                ldm_x4(ah[i], sAh + aBase[i] + (uint32_t)((slA ^ ax[i]) << 4));
            #pragma unroll
            for (int jj = 0; jj < 4; ++jj) {
                uint32_t t[4];
                ldm_x4(t, sB + bBase[jj] + (uint32_t)((slB ^ bx[jj]) << 4));
                bf[2*jj][0] = t[0]; bf[2*jj][1] = t[1];
                bf[2*jj+1][0] = t[2]; bf[2*jj+1][1] = t[3];
            }
            #pragma unroll
            for (int i = 0; i < 4; ++i)
                #pragma unroll
                for (int j = 0; j < 8; ++j)
                    mma16816(acc[i][j], ah[i], bf[j]);
        }
        __syncthreads();
    }

    // epilogue: Q (n<1024) or K (n>=1024), fp16 out
    if (n0 < CC) {
        uint32_t* qh32 = reinterpret_cast<uint32_t*>(g_qh);
        #pragma unroll
        for (int i = 0; i < 4; ++i) {
            const int m = m0 + wm * 64 + i * 16 + (l >> 2);
            #pragma unroll
            for (int j = 0; j < 8; ++j) {
                const int n = n0 + wn * 64 + j * 8 + 2 * (l & 3);
                const float b0 = bias[n], b1 = bias[n + 1];
                size_t off = (size_t)m * CC + n;
                qh32[off >> 1] = pack_f16(acc[i][j][0] + b0, acc[i][j][1] + b1);
                qh32[(off + (size_t)8 * CC) >> 1] = pack_f16(acc[i][j][2] + b0, acc[i][j][3] + b1);
            }
        }
    } else {
        uint32_t* kh32 = reinterpret_cast<uint32_t*>(g_kh);
        #pragma unroll
        for (int i = 0; i < 4; ++i) {
            const int m = m0 + wm * 64 + i * 16 + (l >> 2);
            const int bsel = m >> 11, t = m & 2047;
            #pragma unroll
            for (int j = 0; j < 8; ++j) {
                const int n = n0 + wn * 64 + j * 8 + 2 * (l & 3);
                const int h = (n >> 6) & 15, d = n & 63;
                const float b0 = bias[n], b1 = bias[n + 1];
                size_t off = (((size_t)(bsel * HH + h) * TT + t) * DHH + d);
                kh32[off >> 1] = pack_f16(acc[i][j][0] + b0, acc[i][j][1] + b1);
                kh32[(off + (size_t)8 * DHH) >> 1] = pack_f16(acc[i][j][2] + b0, acc[i][j][3] + b1);
            }
        }
    }
}

// -------------------- gemm_fp16x2 (128x128, 3-stage): V + oproj -------------
// mode 0: fp32 C out; mode 1 with nbase=2048: V fp16 hi/lo transposed epilogue
#define TILEB 16384
#define GST (3 * TILEB)
#define SMEM_GEMM (3 * GST)   // 144 KB

__global__ void __launch_bounds__(256, 1) gemm_fp16x2(
    const __half* __restrict__ Ah, const __half* __restrict__ Al,
    const __half* __restrict__ B,
    const float* __restrict__ bias, float* __restrict__ C, int ldc,
    int mode, int nbase)
{
    extern __shared__ char dsm[];
    const uint32_t sbase = smem_u32(dsm);
    const int tid = threadIdx.x;
    const int l   = tid & 31;
    const int wid = tid >> 5;
    const int wm  = wid & 1;
    const int wn  = wid >> 1;
    const int m0  = blockIdx.x * 128;
    const int n0  = nbase + blockIdx.y * 128;

    const __half* gptr[12];
    uint32_t srel[12];
    {
        const __half* bases[3] = {Ah, Al, B};
        #pragma unroll
        for (int it = 0; it < 12; ++it) {
            int g = it * 256 + tid;
            int tile = g >> 10;
            int r = (g >> 3) & 127;
            int slot = g & 7;
            int row0 = (tile < 2) ? m0 : n0;
            gptr[it] = bases[tile] + (size_t)(row0 + r) * CC + slot * 8;
            srel[it] = tile * TILEB + r * 128 + ((slot ^ (r & 7)) << 4);
        }
    }

    const int hA = l >> 4;
    uint32_t aBase[4]; int ax[4];
    #pragma unroll
    for (int i = 0; i < 4; ++i) {
        int rr = wm * 64 + (l & 15) + i * 16;
        aBase[i] = (uint32_t)(rr * 128); ax[i] = rr & 7;
    }
    const int hB = (l >> 3) & 1;
    uint32_t bBase[2]; int bx[2];
    #pragma unroll
    for (int j = 0; j < 2; ++j) {
        int rr = wn * 32 + ((l & 7) | ((l >> 4) << 3)) + j * 16;
        bBase[j] = (uint32_t)(rr * 128); bx[j] = rr & 7;
    }

    float acc[4][4][4] = {};

    #pragma unroll
    for (int pc = 0; pc < 2; ++pc) {
        const uint32_t sb2 = sbase + pc * GST;
        const int kadv = pc * KCH;
        #pragma unroll
        for (int it = 0; it < 12; ++it) cp16(sb2 + srel[it], gptr[it] + kadv);
        CP_COMMIT();
    }

    int stage = 0;
    for (int c = 0; c < NCH; ++c) {
        if (c + 1 < NCH) CP_WAIT1(); else CP_WAIT0();
        __syncthreads();
        if (c + 2 < NCH) {
            const int sn = (stage + 2 >= 3) ? stage - 1 : stage + 2;
            const uint32_t sb2 = sbase + sn * GST;
            const int kadv = (c + 2) * KCH;
            #pragma unroll
            for (int it = 0; it < 12; ++it) cp16(sb2 + srel[it], gptr[it] + kadv);
            CP_COMMIT();
        }

        const uint32_t st = sbase + stage * GST;
        const uint32_t sAh = st, sAl = st + TILEB, sB = st + 2 * TILEB;
        #pragma unroll
        for (int ks = 0; ks < 4; ++ks) {
            const int slA = ks * 2 + hA;
            const int slB = ks * 2 + hB;
            uint32_t ah[4][4], al_[4][4], bf[4][2];
            #pragma unroll
            for (int i = 0; i < 4; ++i) {
                uint32_t off = aBase[i] + (uint32_t)((slA ^ ax[i]) << 4);
                ldm_x4(ah[i],  sAh + off);
                ldm_x4(al_[i], sAl + off);
            }
            #pragma unroll
            for (int j = 0; j < 2; ++j) {
                uint32_t t[4];
                ldm_x4(t, sB + bBase[j] + (uint32_t)((slB ^ bx[j]) << 4));
                bf[2*j][0] = t[0]; bf[2*j][1] = t[1];
                bf[2*j+1][0] = t[2]; bf[2*j+1][1] = t[3];
            }
            #pragma unroll
            for (int i = 0; i < 4; ++i)
                #pragma unroll
                for (int j = 0; j < 4; ++j) {
                    mma16816(acc[i][j], ah[i],  bf[j]);
                    mma16816(acc[i][j], al_[i], bf[j]);
                }
        }
        stage = (stage + 1 == 3) ? 0 : stage + 1;
    }

    if (mode == 0) {
        #pragma unroll
        for (int i = 0; i < 4; ++i) {
            const int m = m0 + wm * 64 + i * 16 + (l >> 2);
            #pragma unroll
            for (int j = 0; j < 4; ++j) {
                const int n = n0 + wn * 32 + j * 8 + 2 * (l & 3);
                const float b0 = bias[n], b1 = bias[n + 1];
                float2 v0 = { acc[i][j][0] + b0, acc[i][j][1] + b1 };
                float2 v1 = { acc[i][j][2] + b0, acc[i][j][3] + b1 };
                *reinterpret_cast<float2*>(&C[(size_t)m * ldc + n]) = v0;
                *reinterpret_cast<float2*>(&C[(size_t)(m + 8) * ldc + n]) = v1;
            }
        }
    } else {
        // V: fp16 hi/lo transposed [bh][d][t]
        #pragma unroll
        for (int i = 0; i < 4; ++i) {
            const int m = m0 + wm * 64 + i * 16 + (l >> 2);
            const int bsel = m >> 11, t = m & 2047;
            #pragma unroll
            for (int j = 0; j < 4; ++j) {
                const int n = n0 + wn * 32 + j * 8 + 2 * (l & 3);
                const int h = (n >> 6) & 15, d = n & 63;
                const float b0 = bias[n], b1 = bias[n + 1];
                size_t base = ((size_t)(bsel * HH + h) * DHH + d) * TT + t;
                float v0 = acc[i][j][0] + b0, v1 = acc[i][j][1] + b1;
                float v2 = acc[i][j][2] + b0, v3 = acc[i][j][3] + b1;
                __half h0 = __float2half_rn(v0);
                __half h1 = __float2half_rn(v1);
                __half h2 = __float2half_rn(v2);
                __half h3 = __float2half_rn(v3);
                g_vth[base]          = h0;
                g_vth[base + TT]     = h1;
                g_vth[base + 8]      = h2;
                g_vth[base + TT + 8] = h3;
                g_vtl[base]          = __float2half_rn(v0 - __half2float(h0));
                g_vtl[base + TT]     = __float2half_rn(v1 - __half2float(h1));
                g_vtl[base + 8]      = __float2half_rn(v2 - __half2float(h2));
                g_vtl[base + TT + 8] = __float2half_rn(v3 - __half2float(h3));
            }
        }
    }
}

// ------------------------------- mma flash attention (3-stage cp.async) -----
#define ASTG 24576
#define QOFF (3 * ASTG)               // 73728
#define SMEM_ATTN (QOFF + 16384)      // 90112

__global__ void __launch_bounds__(256, 1) attn_mma(
    __half* __restrict__ ath, __half* __restrict__ atl)
{
    extern __shared__ char smem[];
    const uint32_t sb = smem_u32(smem);
    const int tid = threadIdx.x;
    const int l   = tid & 31;
    const int wq  = tid >> 5;
    const int bh  = blockIdx.y;
    const int b   = bh >> 4, h = bh & 15;
    const int qt  = gridDim.x - 1 - blockIdx.x;
    const int q0  = qt * 128;

    // Q cp.async (fp16 pre-scaled), group 0
    const __half* qg = g_qh + ((size_t)(b * TT + q0)) * CC + h * DHH;
    #pragma unroll
    for (int it = 0; it < 4; ++it) {
        int id = it * 256 + tid;
        int row = id >> 3, sl = id & 7;
        cp16(sb + QOFF + (uint32_t)(row * 128 + ((sl ^ (row & 7)) << 4)),
             qg + (size_t)row * CC + sl * 8);
    }
    CP_COMMIT();

    const __half* kh_b  = g_kh  + (size_t)bh * TT * DHH;
    const __half* vth_b = g_vth + (size_t)bh * DHH * TT;
    const __half* vtl_b = g_vtl + (size_t)bh * DHH * TT;
    const __half* gb[6];
    int stp[6];
    uint32_t drel[6];
    #pragma unroll
    for (int it = 0; it < 6; ++it) {
        int id = it * 256 + tid;
        int part = id >> 9;
        int r = (id >> 3) & 63;
        int s2 = id & 7;
        if (part == 0)      { gb[it] = kh_b  + r * DHH + s2 * 8; stp[it] = 64 * DHH; }
        else if (part == 1) { gb[it] = vth_b + (size_t)r * TT + s2 * 8; stp[it] = 64; }
        else                { gb[it] = vtl_b + (size_t)r * TT + s2 * 8; stp[it] = 64; }
        drel[it] = (uint32_t)(part * 8192 + r * 128 + ((s2 ^ (r & 7)) << 4));
    }

    const int ntiles = 2 * (qt + 1);
    #pragma unroll
    for (int pc = 0; pc < 2; ++pc) {
        const uint32_t sb2 = sb + pc * ASTG;
        #pragma unroll
        for (int it = 0; it < 6; ++it) cp16(sb2 + drel[it], gb[it] + pc * stp[it]);
        CP_COMMIT();
    }

    CP_WAIT2();
    __syncthreads();
    uint32_t qh[4][4];
    {
        int row = wq * 16 + (l & 15);
        uint32_t rbase = (uint32_t)(QOFF + row * 128);
        int rx = row & 7;
        #pragma unroll
        for (int kb = 0; kb < 4; ++kb) {
            int s = kb * 2 + (l >> 4);
            ldm_x4(qh[kb], sb + rbase + (uint32_t)((s ^ rx) << 4));
        }
    }

    float o[8][4] = {};
    float m0 = -INFINITY, m1 = -INFINITY, ls0 = 0.f, ls1 = 0.f;
    const int qr0 = q0 + wq * 16 + (l >> 2);
    const int qr1 = qr0 + 8;

    int stage = 0;
    for (int ti = 0; ti < ntiles; ++ti) {
        const int j0 = ti * 64;
        if (ti + 1 < ntiles) CP_WAIT1(); else CP_WAIT0();
        __syncthreads();
        if (ti + 2 < ntiles) {
            const int sn = (stage + 2 >= 3) ? stage - 1 : stage + 2;
            const uint32_t sb2 = sb + sn * ASTG;
            #pragma unroll
            for (int it = 0; it < 6; ++it) cp16(sb2 + drel[it], gb[it] + (ti + 2) * stp[it]);
            CP_COMMIT();
        }
        const uint32_t stK = sb + stage * ASTG;
        const uint32_t stVH = stK + 8192, stVL = stK + 16384;

        float s[8][4] = {};
        {
            int rbl = (l >> 4) * 8 + (l & 7);
            int sbit = (l >> 3) & 1;
            #pragma unroll
            for (int nbp = 0; nbp < 4; ++nbp) {
                int row = nbp * 16 + rbl;
                uint32_t rbase = (uint32_t)(row * 128);
                int rx = row & 7;
                #pragma unroll
                for (int kb = 0; kb < 4; ++kb) {
                    int sl = kb * 2 + sbit;
                    uint32_t off = rbase + (uint32_t)((sl ^ rx) << 4);
                    uint32_t bk4[4];
                    ldm_x4(bk4, stK + off);
                    mma16816(s[2 * nbp],     qh[kb], bk4);
                    mma16816(s[2 * nbp + 1], qh[kb], bk4 + 2);
                }
            }
        }

        if (j0 >= q0) {
            #pragma unroll
            for (int nb = 0; nb < 8; ++nb) {
                int k0i = j0 + nb * 8 + 2 * (l & 3);
                if (k0i     > qr0) s[nb][0] = -INFINITY;
                if (k0i + 1 > qr0) s[nb][1] = -INFINITY;
                if (k0i     > qr1) s[nb][2] = -INFINITY;
                if (k0i + 1 > qr1) s[nb][3] = -INFINITY;
            }
        }

        float mx0 = -INFINITY, mx1 = -INFINITY;
        #pragma unroll
        for (int nb = 0; nb < 8; ++nb) {
            mx0 = fmaxf(mx0, fmaxf(s[nb][0], s[nb][1]));
            mx1 = fmaxf(mx1, fmaxf(s[nb][2], s[nb][3]));
        }
        mx0 = fmaxf(mx0, __shfl_xor_sync(0xffffffffu, mx0, 1));
        mx0 = fmaxf(mx0, __shfl_xor_sync(0xffffffffu, mx0, 2));
        mx1 = fmaxf(mx1, __shfl_xor_sync(0xffffffffu, mx1, 1));
        mx1 = fmaxf(mx1, __shfl_xor_sync(0xffffffffu, mx1, 2));
        float nm0 = fmaxf(m0, mx0), nm1 = fmaxf(m1, mx1);
        float c0 = __expf(m0 - nm0), c1 = __expf(m1 - nm1);
        ls0 *= c0; ls1 *= c1;
        #pragma unroll
        for (int db = 0; db < 8; ++db) {
            o[db][0] *= c0; o[db][1] *= c0;
            o[db][2] *= c1; o[db][3] *= c1;
        }
        float r0 = 0.f, r1 = 0.f;
        #pragma unroll
        for (int nb = 0; nb < 8; ++nb) {
            s[nb][0] = __expf(s[nb][0] - nm0);
            s[nb][1] = __expf(s[nb][1] - nm0);
            s[nb][2] = __expf(s[nb][2] - nm1);
            s[nb][3] = __expf(s[nb][3] - nm1);
            r0 += s[nb][0] + s[nb][1];
            r1 += s[nb][2] + s[nb][3];
        }
        r0 += __shfl_xor_sync(0xffffffffu, r0, 1);
        r0 += __shfl_xor_sync(0xffffffffu, r0, 2);
        r1 += __shfl_xor_sync(0xffffffffu, r1, 1);
        r1 += __shfl_xor_sync(0xffffffffu, r1, 2);
        ls0 += r0; ls1 += r1;
        m0 = nm0; m1 = nm1;

        uint32_t pa[4][4];
        #pragma unroll
        for (int kp = 0; kp < 4; ++kp) {
            pa[kp][0] = pack_f16(s[2 * kp][0],     s[2 * kp][1]);
            pa[kp][1] = pack_f16(s[2 * kp][2],     s[2 * kp][3]);
            pa[kp][2] = pack_f16(s[2 * kp + 1][0], s[2 * kp + 1][1]);
            pa[kp][3] = pack_f16(s[2 * kp + 1][2], s[2 * kp + 1][3]);
        }

        {
            int rbl = (l >> 4) * 8 + (l & 7);
            int sbit = (l >> 3) & 1;
            #pragma unroll
            for (int dbp = 0; dbp < 4; ++dbp) {
                int row = dbp * 16 + rbl;
                uint32_t rbase = (uint32_t)(row * 128);
                int rx = row & 7;
                #pragma unroll
                for (int kp = 0; kp < 4; ++kp) {
                    int sl = kp * 2 + sbit;
                    uint32_t off = rbase + (uint32_t)((sl ^ rx) << 4);
                    uint32_t vh4[4], vl4[4];
                    ldm_x4(vh4, stVH + off);
                    ldm_x4(vl4, stVL + off);
                    mma16816(o[2 * dbp],     pa[kp], vh4);
                    mma16816(o[2 * dbp],     pa[kp], vl4);
                    mma16816(o[2 * dbp + 1], pa[kp], vh4 + 2);
                    mma16816(o[2 * dbp + 1], pa[kp], vl4 + 2);
                }
            }
        }
        stage = (stage + 1 == 3) ? 0 : stage + 1;
    }

    const float inv0 = 1.0f / ls0, inv1 = 1.0f / ls1;
    uint32_t* oh0 = (uint32_t*)(ath + ((size_t)(b * TT + qr0)) * CC + h * DHH);
    uint32_t* ol0 = (uint32_t*)(atl + ((size_t)(b * TT + qr0)) * CC + h * DHH);
    uint32_t* oh1 = (uint32_t*)(ath + ((size_t)(b * TT + qr1)) * CC + h * DHH);
    uint32_t* ol1 = (uint32_t*)(atl + ((size_t)(b * TT + qr1)) * CC + h * DHH);
    #pragma unroll
    for (int db = 0; db < 8; ++db) {
        int cidx = (db * 8 + 2 * (l & 3)) >> 1;
        uint32_t hp, lp;
        split2h(o[db][0] * inv0, o[db][1] * inv0, hp, lp);
        oh0[cidx] = hp; ol0[cidx] = lp;
        split2h(o[db][2] * inv1, o[db][3] * inv1, hp, lp);
        oh1[cidx] = hp; ol1[cidx] = lp;
    }
}

// ------------------------------- launch -------------------------------------
extern "C" void kernel_launch(void* const* d_in, const int* in_sizes, int n_in,
                              void* d_out, int out_size) {
    const float* x  = (const float*)d_in[0];
    const float* Wq = (const float*)d_in[1];
    const float* bq = (const float*)d_in[2];
    const float* Wk = (const float*)d_in[3];
    const float* bk = (const float*)d_in[4];
    const float* Wv = (const float*)d_in[5];
    const float* bv = (const float*)d_in[6];
    const float* Wo = (const float*)d_in[7];
    const float* bo = (const float*)d_in[8];
    float* out = (float*)d_out;

    cudaFuncSetAttribute(gemm_qk,     cudaFuncAttributeMaxDynamicSharedMemorySize, SMEM_QK);
    cudaFuncSetAttribute(gemm_fp16x2, cudaFuncAttributeMaxDynamicSharedMemorySize, SMEM_GEMM);
    cudaFuncSetAttribute(attn_mma,    cudaFuncAttributeMaxDynamicSharedMemorySize, SMEM_ATTN);

    float *biasp;
    __half *xh, *xl, *wt, *wot, *ath, *atl;
    cudaGetSymbolAddress((void**)&xh, g_xh);
    cudaGetSymbolAddress((void**)&xl, g_xl);
    cudaGetSymbolAddress((void**)&wt, g_wt);
    cudaGetSymbolAddress((void**)&wot, g_wot);
    cudaGetSymbolAddress((void**)&biasp, g_bias);
    cudaGetSymbolAddress((void**)&ath, g_ath);
    cudaGetSymbolAddress((void**)&atl, g_atl);

    int n4 = MROWS * CC / 4;
    conv_split<<<n4 / 256, 256>>>((const float4*)x, (uint32_t*)xh, (uint32_t*)xl, n4);
    repack_qkv<<<NQKV, 256>>>(Wq, Wk, Wv, bq, bk, bv);
    repack_wo<<<CC, 256>>>(Wo);

    // Q,K: 1-pass wide-N gemm (n0 = 0..2048 in 256 steps)
    gemm_qk<<<dim3(MROWS / 128, (2 * CC) / 256), 256, SMEM_QK>>>(xh, wt, biasp);

    // V: 2-pass, fused transpose/split epilogue (n0 = 2048..3072)
    gemm_fp16x2<<<dim3(MROWS / 128, CC / 128), 256, SMEM_GEMM>>>(
        xh, xl, wt, biasp, nullptr, 0, 1, 2 * CC);

    attn_mma<<<dim3(TT / 128, BB * HH), 256, SMEM_ATTN>>>(ath, atl);

    // output projection: fp32 out
    gemm_fp16x2<<<dim3(MROWS / 128, CC / 128), 256, SMEM_GEMM>>>(
        ath, atl, wot, bo, out, CC, 0, 0);
}